// round 3
// baseline (speedup 1.0000x reference)
#include <cuda_runtime.h>
#include <cuda_bf16.h>

// GCN 2-layer: out = log_softmax( Agg( relu(Agg(x@W1)+b1) @ W2 ) + b2 )
// Agg = D^-1/2 (A+I) D^-1/2, in-degree (incl self loop) sym norm.
// edge_index dtype is detected at runtime (int64 vs int32 downcast by harness).

#define NN 100000
#define EE 3200000
#define DIN 128
#define DH 16

// ---- scratch (static device globals; no allocations allowed) ----
__device__ __align__(16) int   g_cnt[NN];
__device__ __align__(16) float g_dinv[NN];
__device__ __align__(16) int   g_src[EE];
__device__ __align__(16) int   g_dst[EE];
__device__ __align__(16) float g_h1[NN * DH];     // x @ W1
__device__ __align__(16) float g_agg1[NN * DH];   // scatter target layer 1
__device__ __align__(16) float g_t[NN * 2];       // relu(agg1+self) @ W2
__device__ __align__(16) float g_agg2[NN * 2];    // scatter target layer 2
__device__ int g_is64;

// K-1: detect whether edge buffer is int64 (odd 32-bit words all zero) or int32
__global__ void k_detect(const unsigned int* __restrict__ ei32) {
    if (threadIdx.x == 0 && blockIdx.x == 0) {
        int nz = 0;
        #pragma unroll
        for (int i = 0; i < 64; i++) nz += (ei32[2 * i + 1] != 0u);
        g_is64 = (nz == 0) ? 1 : 0;
    }
}

// K0: zero scratch
__global__ void k_zero(int n16, int n2, int n) {
    int i = blockIdx.x * blockDim.x + threadIdx.x;
    if (i < n16) g_agg1[i] = 0.f;
    if (i < n2)  g_agg2[i] = 0.f;
    if (i < n)   g_cnt[i]  = 0;
}

// K1: parse edge index (either dtype) -> int32 arrays, count in-degree
__global__ void k_deg(const int* __restrict__ ei, int E) {
    int e = blockIdx.x * blockDim.x + threadIdx.x;
    if (e >= E) return;
    int s, d;
    if (g_is64) {                    // int64 little-endian: take low words
        s = ei[2 * e];
        d = ei[2 * (E + e)];
    } else {                         // int32
        s = ei[e];
        d = ei[E + e];
    }
    g_src[e] = s;
    g_dst[e] = d;
    atomicAdd(&g_cnt[d], 1);
}

// K2: dinv = rsqrt(deg + 1)  (self loop)
__global__ void k_dinv(int N) {
    int n = blockIdx.x * blockDim.x + threadIdx.x;
    if (n >= N) return;
    g_dinv[n] = rsqrtf((float)(g_cnt[n] + 1));
}

// K3: h1 = x @ W1   (16 nodes x 16 cols per 256-thread block)
__global__ void k_gemm1(const float* __restrict__ x, const float* __restrict__ W1, int N) {
    __shared__ float w[DIN * DH];
    int tid = threadIdx.x;
    #pragma unroll
    for (int i = tid; i < DIN * DH; i += 256) w[i] = W1[i];
    __syncthreads();
    int n = blockIdx.x * 16 + (tid >> 4);
    int j = tid & 15;
    if (n >= N) return;
    const float4* x4 = (const float4*)(x + (size_t)n * DIN);
    float acc = 0.f;
    #pragma unroll
    for (int k = 0; k < DIN / 4; k++) {
        float4 v = x4[k];
        acc = fmaf(v.x, w[(4 * k + 0) * DH + j], acc);
        acc = fmaf(v.y, w[(4 * k + 1) * DH + j], acc);
        acc = fmaf(v.z, w[(4 * k + 2) * DH + j], acc);
        acc = fmaf(v.w, w[(4 * k + 3) * DH + j], acc);
    }
    g_h1[n * DH + j] = acc;
}

// K4: layer-1 edge scatter: agg1[d] += h1[s] * dinv[s]*dinv[d]  (4x float4 RED)
__global__ void k_scatter1(int E) {
    int e = blockIdx.x * blockDim.x + threadIdx.x;
    if (e >= E) return;
    int s = g_src[e];
    int d = g_dst[e];
    float wgt = g_dinv[s] * g_dinv[d];
    const float4* hs = (const float4*)(g_h1 + (size_t)s * DH);
    float4* ad = (float4*)(g_agg1 + (size_t)d * DH);
    #pragma unroll
    for (int g = 0; g < 4; g++) {
        float4 v = hs[g];
        atomicAdd(&ad[g], make_float4(v.x * wgt, v.y * wgt, v.z * wgt, v.w * wgt));
    }
}

// K5: self loop + b1 + relu, then t = v @ W2
__global__ void k_mid(const float* __restrict__ b1, const float* __restrict__ W2, int N) {
    __shared__ float w2[DH * 2];
    __shared__ float sb1[DH];
    if (threadIdx.x < DH * 2) w2[threadIdx.x] = W2[threadIdx.x];
    if (threadIdx.x < DH) sb1[threadIdx.x] = b1[threadIdx.x];
    __syncthreads();
    int n = blockIdx.x * blockDim.x + threadIdx.x;
    if (n >= N) return;
    float di = g_dinv[n];
    float selfw = di * di;
    float t0 = 0.f, t1 = 0.f;
    #pragma unroll
    for (int i = 0; i < DH; i++) {
        float v = g_agg1[n * DH + i] + g_h1[n * DH + i] * selfw + sb1[i];
        v = fmaxf(v, 0.f);
        t0 = fmaf(v, w2[i * 2 + 0], t0);
        t1 = fmaf(v, w2[i * 2 + 1], t1);
    }
    ((float2*)g_t)[n] = make_float2(t0, t1);
}

// K6: layer-2 edge scatter: agg2[d] += t[s] * norm  (1x float2 RED)
__global__ void k_scatter2(int E) {
    int e = blockIdx.x * blockDim.x + threadIdx.x;
    if (e >= E) return;
    int s = g_src[e];
    int d = g_dst[e];
    float wgt = g_dinv[s] * g_dinv[d];
    float2 tv = ((const float2*)g_t)[s];
    atomicAdd(&((float2*)g_agg2)[d], make_float2(tv.x * wgt, tv.y * wgt));
}

// K7: self loop + b2, log_softmax over 2 classes
__global__ void k_final(const float* __restrict__ b2, float* __restrict__ out, int N) {
    int n = blockIdx.x * blockDim.x + threadIdx.x;
    if (n >= N) return;
    float di = g_dinv[n];
    float selfw = di * di;
    float2 tv = ((const float2*)g_t)[n];
    float2 av = ((const float2*)g_agg2)[n];
    float v0 = av.x + tv.x * selfw + b2[0];
    float v1 = av.y + tv.y * selfw + b2[1];
    float m = fmaxf(v0, v1);
    float lse = m + logf(expf(v0 - m) + expf(v1 - m));
    out[2 * n + 0] = v0 - lse;
    out[2 * n + 1] = v1 - lse;
}

extern "C" void kernel_launch(void* const* d_in, const int* in_sizes, int n_in,
                              void* d_out, int out_size) {
    // Positional defaults (setup_inputs order), overridden by unique size match.
    const float* x  = (n_in > 0) ? (const float*)d_in[0] : 0;
    const float* W1 = (n_in > 1) ? (const float*)d_in[1] : 0;
    const float* b1 = (n_in > 2) ? (const float*)d_in[2] : 0;
    const float* W2 = (n_in > 3) ? (const float*)d_in[3] : 0;
    const float* b2 = (n_in > 4) ? (const float*)d_in[4] : 0;
    const void*  ei = (n_in > 5) ? d_in[5] : 0;
    int E = EE, N = NN;
    for (int i = 0; i < n_in; i++) {
        long long sz = in_sizes[i];
        if (sz == (long long)NN * DIN)      x  = (const float*)d_in[i];
        else if (sz == DIN * DH)            W1 = (const float*)d_in[i];
        else if (sz == DH)                  b1 = (const float*)d_in[i];
        else if (sz == DH * 2)              W2 = (const float*)d_in[i];
        else if (sz == 2)                   b2 = (const float*)d_in[i];
        else if (sz == 2LL * EE)          { ei = d_in[i]; E = (int)(sz / 2); }
    }
    float* out = (float*)d_out;

    const int T = 256;
    int zmax = N * DH;
    k_detect<<<1, 32>>>((const unsigned int*)ei);
    k_zero<<<(zmax + T - 1) / T, T>>>(N * DH, N * 2, N);
    k_deg<<<(E + T - 1) / T, T>>>((const int*)ei, E);
    k_dinv<<<(N + T - 1) / T, T>>>(N);
    k_gemm1<<<(N + 15) / 16, T>>>(x, W1, N);
    k_scatter1<<<(E + T - 1) / T, T>>>(E);
    k_mid<<<(N + T - 1) / T, T>>>(b1, W2, N);
    k_scatter2<<<(E + T - 1) / T, T>>>(E);
    k_final<<<(N + T - 1) / T, T>>>(b2, out, N);
}

// round 4
// speedup vs baseline: 1.3548x; 1.3548x over previous
#include <cuda_runtime.h>
#include <cuda_bf16.h>

// GCN 2-layer via on-the-fly CSR (scatter -> gather, no float atomics):
// out = log_softmax( Agg( relu(Agg(x@W1)+b1) @ W2 ) + b2 )
// Agg = D^-1/2 (A+I) D^-1/2. Prescale trick: h1p = (x@W1)*dinv,
// agg1[d] = dinv[d]*(sum_adj h1p[s] + h1p[d]); same for layer 2 with tp.

#define NN 100000
#define EE 3200000
#define DIN 128
#define DH 16
#define NB ((NN + 255) / 256)   // 391 scan blocks

// ---- scratch (static device globals; no allocations allowed) ----
__device__ __align__(16) int   g_cnt[NN];
__device__ __align__(16) float g_dinv[NN];
__device__ __align__(16) int   g_off[NN + 1];
__device__ __align__(16) int   g_cur[NN];
__device__ __align__(16) int   g_bsum[512];
__device__ __align__(16) int   g_adj[EE];
__device__ __align__(16) float g_h1p[NN * DH];   // (x@W1) * dinv  (6.4MB, L2-resident)
__device__ __align__(16) float g_tp[NN * 2];     // t * dinv
__device__ int g_is64;

// detect int64 vs int32 edge buffer (int64 -> high words of ids < 100000 are 0)
__global__ void k_detect(const unsigned int* __restrict__ ei32) {
    if (threadIdx.x == 0) {
        int nz = 0;
        #pragma unroll
        for (int i = 0; i < 64; i++) nz += (ei32[2 * i + 1] != 0u);
        g_is64 = (nz == 0) ? 1 : 0;
    }
}

__global__ void k_zero(int N) {
    int i = blockIdx.x * blockDim.x + threadIdx.x;
    if (i < N) g_cnt[i] = 0;
}

// parse edges, count in-degree (int atomics only)
__global__ void k_deg(const int* __restrict__ ei, int E) {
    int e = blockIdx.x * blockDim.x + threadIdx.x;
    if (e >= E) return;
    int d = g_is64 ? ei[2 * (E + e)] : ei[E + e];
    atomicAdd(&g_cnt[d], 1);
}

__global__ void k_dinv(int N) {
    int n = blockIdx.x * blockDim.x + threadIdx.x;
    if (n >= N) return;
    g_dinv[n] = rsqrtf((float)(g_cnt[n] + 1));
}

// --- 3-phase exclusive scan of g_cnt -> g_off ---
__global__ void k_scan1(int N) {
    __shared__ int s[256];
    int i = blockIdx.x * 256 + threadIdx.x;
    int v = (i < N) ? g_cnt[i] : 0;
    s[threadIdx.x] = v;
    __syncthreads();
    #pragma unroll
    for (int o = 1; o < 256; o <<= 1) {
        int t = (threadIdx.x >= o) ? s[threadIdx.x - o] : 0;
        __syncthreads();
        s[threadIdx.x] += t;
        __syncthreads();
    }
    int incl = s[threadIdx.x];
    if (i < N) g_off[i] = incl - v;          // exclusive within block
    if (threadIdx.x == 255) g_bsum[blockIdx.x] = incl;
}

__global__ void k_scan2(int nb) {
    __shared__ int s[512];
    int v = (threadIdx.x < nb) ? g_bsum[threadIdx.x] : 0;
    s[threadIdx.x] = v;
    __syncthreads();
    #pragma unroll
    for (int o = 1; o < 512; o <<= 1) {
        int t = (threadIdx.x >= o) ? s[threadIdx.x - o] : 0;
        __syncthreads();
        s[threadIdx.x] += t;
        __syncthreads();
    }
    if (threadIdx.x < nb) g_bsum[threadIdx.x] = s[threadIdx.x] - v;  // exclusive
}

__global__ void k_scan3(int N, int E) {
    int i = blockIdx.x * 256 + threadIdx.x;
    if (i < N) {
        int o = g_off[i] + g_bsum[blockIdx.x];
        g_off[i] = o;
        g_cur[i] = o;
    }
    if (i == 0) g_off[N] = E;
}

// bucket pass: build adjacency (srcs grouped by dst)
__global__ void k_bucket(const int* __restrict__ ei, int E) {
    int e = blockIdx.x * blockDim.x + threadIdx.x;
    if (e >= E) return;
    int s, d;
    if (g_is64) { s = ei[2 * e]; d = ei[2 * (E + e)]; }
    else        { s = ei[e];     d = ei[E + e]; }
    int pos = atomicAdd(&g_cur[d], 1);
    g_adj[pos] = s;
}

// h1p = (x @ W1) * dinv   (16 nodes x 16 cols per 256-thread block)
__global__ void k_gemm1(const float* __restrict__ x, const float* __restrict__ W1, int N) {
    __shared__ float w[DIN * DH];
    int tid = threadIdx.x;
    #pragma unroll
    for (int i = tid; i < DIN * DH; i += 256) w[i] = W1[i];
    __syncthreads();
    int n = blockIdx.x * 16 + (tid >> 4);
    int j = tid & 15;
    if (n >= N) return;
    const float4* x4 = (const float4*)(x + (size_t)n * DIN);
    float acc = 0.f;
    #pragma unroll
    for (int k = 0; k < DIN / 4; k++) {
        float4 v = x4[k];
        acc = fmaf(v.x, w[(4 * k + 0) * DH + j], acc);
        acc = fmaf(v.y, w[(4 * k + 1) * DH + j], acc);
        acc = fmaf(v.z, w[(4 * k + 2) * DH + j], acc);
        acc = fmaf(v.w, w[(4 * k + 3) * DH + j], acc);
    }
    g_h1p[n * DH + j] = acc * g_dinv[n];
}

// layer-1 gather + self + b1 + relu + @W2 + prescale by dinv -> tp
// one warp per node; half-warp per adjacency entry (2 edges in flight)
__global__ void k_agg1(const float* __restrict__ b1, const float* __restrict__ W2, int N) {
    int lane = threadIdx.x & 31;
    int warp = (blockIdx.x * blockDim.x + threadIdx.x) >> 5;
    if (warp >= N) return;
    int d = warp;
    int half = lane >> 4;          // 0 or 1
    int j = lane & 15;             // feature index
    int base = g_off[d];
    int deg = g_off[d + 1] - base;
    float acc = 0.f;
    for (int i = half; i < deg; i += 2) {
        int s = g_adj[base + i];
        acc += g_h1p[s * DH + j];
    }
    acc += __shfl_xor_sync(0xffffffffu, acc, 16);
    float dinv_d = g_dinv[d];
    float v = fmaxf(fmaf(dinv_d, acc + g_h1p[d * DH + j], __ldg(&b1[j])), 0.f);
    float p0 = v * __ldg(&W2[j * 2 + 0]);
    float p1 = v * __ldg(&W2[j * 2 + 1]);
    #pragma unroll
    for (int o = 8; o > 0; o >>= 1) {
        p0 += __shfl_down_sync(0xffffffffu, p0, o, 16);
        p1 += __shfl_down_sync(0xffffffffu, p1, o, 16);
    }
    if (lane == 0)
        ((float2*)g_tp)[d] = make_float2(p0 * dinv_d, p1 * dinv_d);
}

// layer-2 gather + self + b2 + log_softmax -> out
__global__ void k_agg2(const float* __restrict__ b2, float* __restrict__ out, int N) {
    int lane = threadIdx.x & 31;
    int warp = (blockIdx.x * blockDim.x + threadIdx.x) >> 5;
    if (warp >= N) return;
    int d = warp;
    int base = g_off[d];
    int deg = g_off[d + 1] - base;
    float a0 = 0.f, a1 = 0.f;
    for (int i = lane; i < deg; i += 32) {
        int s = g_adj[base + i];
        float2 tv = ((const float2*)g_tp)[s];
        a0 += tv.x;
        a1 += tv.y;
    }
    #pragma unroll
    for (int o = 16; o > 0; o >>= 1) {
        a0 += __shfl_down_sync(0xffffffffu, a0, o);
        a1 += __shfl_down_sync(0xffffffffu, a1, o);
    }
    if (lane == 0) {
        float dinv_d = g_dinv[d];
        float2 tself = ((const float2*)g_tp)[d];
        float v0 = fmaf(dinv_d, a0 + tself.x, __ldg(&b2[0]));
        float v1 = fmaf(dinv_d, a1 + tself.y, __ldg(&b2[1]));
        float m = fmaxf(v0, v1);
        float lse = m + logf(expf(v0 - m) + expf(v1 - m));
        out[2 * d + 0] = v0 - lse;
        out[2 * d + 1] = v1 - lse;
    }
}

extern "C" void kernel_launch(void* const* d_in, const int* in_sizes, int n_in,
                              void* d_out, int out_size) {
    // positional defaults, overridden by unique element-count match
    const float* x  = (n_in > 0) ? (const float*)d_in[0] : 0;
    const float* W1 = (n_in > 1) ? (const float*)d_in[1] : 0;
    const float* b1 = (n_in > 2) ? (const float*)d_in[2] : 0;
    const float* W2 = (n_in > 3) ? (const float*)d_in[3] : 0;
    const float* b2 = (n_in > 4) ? (const float*)d_in[4] : 0;
    const void*  ei = (n_in > 5) ? d_in[5] : 0;
    int E = EE, N = NN;
    for (int i = 0; i < n_in; i++) {
        long long sz = in_sizes[i];
        if (sz == (long long)NN * DIN)      x  = (const float*)d_in[i];
        else if (sz == DIN * DH)            W1 = (const float*)d_in[i];
        else if (sz == DH)                  b1 = (const float*)d_in[i];
        else if (sz == DH * 2)              W2 = (const float*)d_in[i];
        else if (sz == 2)                   b2 = (const float*)d_in[i];
        else if (sz == 2LL * EE)          { ei = d_in[i]; E = (int)(sz / 2); }
    }
    float* out = (float*)d_out;

    const int T = 256;
    int nb = (N + 255) / 256;
    k_detect<<<1, 32>>>((const unsigned int*)ei);
    k_zero<<<nb, T>>>(N);
    k_deg<<<(E + T - 1) / T, T>>>((const int*)ei, E);
    k_dinv<<<nb, T>>>(N);
    k_scan1<<<nb, 256>>>(N);
    k_scan2<<<1, 512>>>(nb);
    k_scan3<<<nb, 256>>>(N, E);
    k_bucket<<<(E + T - 1) / T, T>>>((const int*)ei, E);
    k_gemm1<<<(N + 15) / 16, T>>>(x, W1, N);
    k_agg1<<<(N * 32 + T - 1) / T, T>>>(b1, W2, N);
    k_agg2<<<(N * 32 + T - 1) / T, T>>>(b2, out, N);
}